// round 4
// baseline (speedup 1.0000x reference)
#include <cuda_runtime.h>
#include <cuda_bf16.h>
#include <math.h>

#define NN 100000
#define EG 600000
#define EE 600000

// ---------------- scratch (static device globals; no allocation) ----------------
__device__ float g_h[NN * 64];
__device__ float g_x[NN * 64];
__device__ float g_out[NN * 64];
__device__ float g_as[NN];
__device__ float g_ad[NN];
__device__ unsigned g_amax_key[NN];
__device__ float g_amaxf[NN];
__device__ float g_denom[NN];
__device__ float g_alpha[EG];
__device__ float g_Y[(size_t)NN * 1040];

__device__ __forceinline__ float fast_elu(float v) {
    // jax.nn.elu = x>0 ? x : expm1(x). __expf(v)-1 has abs err ~1e-7, fine at 1e-3 tol.
    return (v > 0.0f) ? v : (__expf(v) - 1.0f);
}

__global__ void zero_scratch() {
    int i = blockIdx.x * blockDim.x + threadIdx.x;
    if (i < NN * 64) g_out[i] = 0.0f;
    if (i < NN) { g_denom[i] = 0.0f; g_amax_key[i] = 0u; }
}

// h = x @ W ; a_s = sum(h*att_s) ; a_d = sum(h*att_d)
template <bool FIRST>
__global__ void node_transform(const float* __restrict__ xin,
                               const float* __restrict__ W,
                               const float* __restrict__ att_s,
                               const float* __restrict__ att_d) {
    const int IN = FIRST ? 3 : 64;
    __shared__ float Ws[64 * 64];
    __shared__ float xs[4][64];
    __shared__ float red_s[4][2];
    __shared__ float red_d[4][2];
    int tid = threadIdx.x; // 256
    for (int i = tid; i < IN * 64; i += 256) Ws[i] = W[i];
    int node0 = blockIdx.x * 4;
    for (int i = tid; i < 4 * IN; i += 256) {
        int g = i / IN, k = i % IN;
        int n = node0 + g;
        const float* src = FIRST ? xin : g_x;
        xs[g][k] = (n < NN) ? src[(size_t)n * IN + k] : 0.0f;
    }
    __syncthreads();
    int c = tid & 63;
    int g = tid >> 6;
    int n = node0 + g;
    float v = 0.0f;
#pragma unroll
    for (int k = 0; k < IN; k++) v = fmaf(xs[g][k], Ws[k * 64 + c], v);
    float ps = v * att_s[c];
    float pd = v * att_d[c];
#pragma unroll
    for (int o = 16; o; o >>= 1) {
        ps += __shfl_down_sync(0xFFFFFFFFu, ps, o);
        pd += __shfl_down_sync(0xFFFFFFFFu, pd, o);
    }
    if ((tid & 31) == 0) { red_s[g][c >> 5] = ps; red_d[g][c >> 5] = pd; }
    if (n < NN) g_h[(size_t)n * 64 + c] = v;
    __syncthreads();
    if (n < NN && c == 0) {
        g_as[n] = red_s[g][0] + red_s[g][1];
        g_ad[n] = red_d[g][0] + red_d[g][1];
    }
}

__device__ __forceinline__ unsigned float_key(float f) {
    unsigned u = __float_as_uint(f);
    return (u & 0x80000000u) ? ~u : (u | 0x80000000u);
}

__global__ void edge_alpha_max(const int* __restrict__ gsrc, const int* __restrict__ gdst) {
    int i = blockIdx.x * blockDim.x + threadIdx.x;
    if (i >= EG) return;
    float a = g_as[gsrc[i]] + g_ad[gdst[i]];
    a = (a >= 0.0f) ? a : 0.2f * a;
    g_alpha[i] = a;
    atomicMax(&g_amax_key[gdst[i]], float_key(a));
}

__global__ void decode_amax() {
    int n = blockIdx.x * blockDim.x + threadIdx.x;
    if (n >= NN) return;
    unsigned k = g_amax_key[n];
    float m;
    if (k == 0u) m = 0.0f;
    else m = (k & 0x80000000u) ? __uint_as_float(k ^ 0x80000000u) : __uint_as_float(~k);
    g_amaxf[n] = m;
}

__global__ void edge_exp_denom(const int* __restrict__ gdst) {
    int i = blockIdx.x * blockDim.x + threadIdx.x;
    if (i >= EG) return;
    int d = gdst[i];
    float e = __expf(g_alpha[i] - g_amaxf[d]);
    g_alpha[i] = e;
    atomicAdd(&g_denom[d], e);
}

// 16 threads per edge; each thread handles one float4 channel-group via v4 reduction
__global__ void edge_scatter(const int* __restrict__ gsrc, const int* __restrict__ gdst) {
    long long idx = (long long)blockIdx.x * blockDim.x + threadIdx.x;
    int e = (int)(idx >> 4);
    if (e >= EG) return;
    int l = (int)(idx & 15);
    int s = gsrc[e], d = gdst[e];
    float w = g_alpha[e] / (g_denom[d] + 1e-16f);
    const float4* hs = (const float4*)(g_h + (size_t)s * 64);
    float4 h = hs[l];
    float4 v = make_float4(h.x * w, h.y * w, h.z * w, h.w * w);
    float* od = g_out + (size_t)d * 64 + 4 * l;
    asm volatile("red.global.add.v4.f32 [%0], {%1,%2,%3,%4};"
                 :: "l"(od), "f"(v.x), "f"(v.y), "f"(v.z), "f"(v.w) : "memory");
}

__global__ void finalize_node(const float* __restrict__ bias) {
    int i = blockIdx.x * blockDim.x + threadIdx.x;
    if (i >= NN * 64) return;
    g_x[i] = fast_elu(g_out[i] + bias[i & 63]);
}

__global__ void gemm_y(const float* __restrict__ Wm1) {
    __shared__ float As[64][65];
    __shared__ float Bs[64][65];
    int bm = blockIdx.y, bn = blockIdx.x;
    int tid = threadIdx.x;
    for (int i = tid; i < 64 * 64; i += 256) {
        int r = i >> 6, k = i & 63;
        int m = bm * 64 + r;
        As[r][k] = (m < NN) ? g_x[(size_t)m * 64 + k] : 0.0f;
    }
    for (int i = tid; i < 64 * 64; i += 256) {
        int k = i >> 6, nl = i & 63;
        int n = bn * 64 + nl;
        float b = 0.0f;
        if (n < 1040) b = (n < 520) ? Wm1[k * 520 + n] : Wm1[(64 + k) * 520 + (n - 520)];
        Bs[k][nl] = b;
    }
    __syncthreads();
    int tx = tid & 15, ty = tid >> 4;
    float acc[4][4] = {};
#pragma unroll
    for (int k = 0; k < 64; k++) {
        float a[4], b[4];
#pragma unroll
        for (int i = 0; i < 4; i++) { a[i] = As[ty * 4 + i][k]; b[i] = Bs[k][tx * 4 + i]; }
#pragma unroll
        for (int i = 0; i < 4; i++)
#pragma unroll
            for (int j = 0; j < 4; j++) acc[i][j] = fmaf(a[i], b[j], acc[i][j]);
    }
#pragma unroll
    for (int i = 0; i < 4; i++) {
        int m = bm * 64 + ty * 4 + i;
        if (m >= NN) continue;
#pragma unroll
        for (int j = 0; j < 4; j++) {
            int n = bn * 64 + tx * 4 + j;
            if (n < 1040) g_Y[(size_t)m * 1040 + n] = acc[i][j];
        }
    }
}

// warp per prediction edge, float4-vectorized over the 520 hidden channels
__global__ void edge_mlp(const int* __restrict__ esrc, const int* __restrict__ edst,
                         const float* __restrict__ ea,
                         const float* __restrict__ Wm1, const float* __restrict__ bm1,
                         const float* __restrict__ Wm2, const float* __restrict__ bm2,
                         float* __restrict__ out) {
    __shared__ float4 sB[130], sW2[130], sC0[130], sC1[130];
    int tid = threadIdx.x; // 256
    if (tid < 130) {
        sB[tid]  = ((const float4*)bm1)[tid];
        sW2[tid] = ((const float4*)Wm2)[tid];
        sC0[tid] = ((const float4*)(Wm1 + 128 * 520))[tid];
        sC1[tid] = ((const float4*)(Wm1 + 129 * 520))[tid];
    }
    __syncthreads();
    int e = (blockIdx.x * 256 + tid) >> 5;
    if (e >= EE) return;
    int lane = tid & 31;
    int s = esrc[e], d = edst[e];
    float a0 = ea[2 * e], a1 = ea[2 * e + 1];
    const float4* ys = (const float4*)(g_Y + (size_t)s * 1040);
    const float4* yd = (const float4*)(g_Y + (size_t)d * 1040 + 520);
    float acc = 0.0f;
    for (int k = lane; k < 130; k += 32) {
        float4 a = ys[k];
        float4 b = yd[k];
        float4 bb = sB[k];
        float4 c0 = sC0[k];
        float4 c1 = sC1[k];
        float4 w2 = sW2[k];
        float v0 = fmaf(a1, c1.x, fmaf(a0, c0.x, a.x + b.x + bb.x));
        float v1 = fmaf(a1, c1.y, fmaf(a0, c0.y, a.y + b.y + bb.y));
        float v2 = fmaf(a1, c1.z, fmaf(a0, c0.z, a.z + b.z + bb.z));
        float v3 = fmaf(a1, c1.w, fmaf(a0, c0.w, a.w + b.w + bb.w));
        acc = fmaf(fast_elu(v0), w2.x, acc);
        acc = fmaf(fast_elu(v1), w2.y, acc);
        acc = fmaf(fast_elu(v2), w2.z, acc);
        acc = fmaf(fast_elu(v3), w2.w, acc);
    }
#pragma unroll
    for (int o = 16; o; o >>= 1) acc += __shfl_down_sync(0xFFFFFFFFu, acc, o);
    if (lane == 0) out[e] = acc + bm2[0];
}

static void run_gat_layer(const float* xin, bool first,
                          const float* W, const float* as, const float* ad, const float* b,
                          const int* gsrc, const int* gdst) {
    zero_scratch<<<(NN * 64 + 255) / 256, 256>>>();
    if (first) node_transform<true><<<(NN + 3) / 4, 256>>>(xin, W, as, ad);
    else       node_transform<false><<<(NN + 3) / 4, 256>>>(xin, W, as, ad);
    edge_alpha_max<<<(EG + 255) / 256, 256>>>(gsrc, gdst);
    decode_amax<<<(NN + 255) / 256, 256>>>();
    edge_exp_denom<<<(EG + 255) / 256, 256>>>(gdst);
    edge_scatter<<<((long long)EG * 16 + 255) / 256, 256>>>(gsrc, gdst);
    finalize_node<<<(NN * 64 + 255) / 256, 256>>>(b);
}

extern "C" void kernel_launch(void* const* d_in, const int* in_sizes, int n_in,
                              void* d_out, int out_size) {
    const float* pos   = (const float*)d_in[0];
    const int*   eidx  = (const int*)d_in[1];
    const int*   geidx = (const int*)d_in[2];
    const float* eattr = (const float*)d_in[3];
    const float* W0    = (const float*)d_in[4];
    const float* as0   = (const float*)d_in[5];
    const float* ad0   = (const float*)d_in[6];
    const float* b0    = (const float*)d_in[7];
    const float* W1    = (const float*)d_in[8];
    const float* as1   = (const float*)d_in[9];
    const float* ad1   = (const float*)d_in[10];
    const float* b1    = (const float*)d_in[11];
    const float* Wm1   = (const float*)d_in[12];
    const float* bm1   = (const float*)d_in[13];
    const float* Wm2   = (const float*)d_in[14];
    const float* bm2   = (const float*)d_in[15];
    float* out = (float*)d_out;

    const int* gsrc = geidx;
    const int* gdst = geidx + EG;
    const int* esrc = eidx;
    const int* edst = eidx + EE;

    run_gat_layer(pos, true,  W0, as0, ad0, b0, gsrc, gdst);
    run_gat_layer(nullptr, false, W1, as1, ad1, b1, gsrc, gdst);

    dim3 ggrid(17, (NN + 63) / 64);
    gemm_y<<<ggrid, 256>>>(Wm1);

    edge_mlp<<<((long long)EE * 32 + 255) / 256, 256>>>(esrc, edst, eattr, Wm1, bm1, Wm2, bm2, out);
}

// round 5
// speedup vs baseline: 1.9605x; 1.9605x over previous
#include <cuda_runtime.h>
#include <cuda_fp16.h>
#include <cuda_bf16.h>
#include <math.h>

#define NN 100000
#define EG 600000
#define EE 600000

// ---------------- scratch (static device globals; no allocation) ----------------
__device__ float g_h[NN * 64];
__device__ float g_x[NN * 64];
__device__ float g_out[NN * 64];
__device__ float g_as[NN];
__device__ float g_ad[NN];
__device__ float g_denom[NN];
__device__ float g_alpha[EG];
__device__ __half g_Yh[(size_t)NN * 1040];   // fp16 Y: halves edge_mlp gather traffic

__device__ __forceinline__ float fast_elu(float v) {
    return (v > 0.0f) ? v : (__expf(v) - 1.0f);
}

__global__ void zero_scratch() {
    int i = blockIdx.x * blockDim.x + threadIdx.x;
    if (i < NN * 64) g_out[i] = 0.0f;
    if (i < NN) g_denom[i] = 0.0f;
}

// h = x @ W ; a_s = sum(h*att_s) ; a_d = sum(h*att_d)
template <bool FIRST>
__global__ void node_transform(const float* __restrict__ xin,
                               const float* __restrict__ W,
                               const float* __restrict__ att_s,
                               const float* __restrict__ att_d) {
    const int IN = FIRST ? 3 : 64;
    __shared__ float Ws[64 * 64];
    __shared__ float xs[4][64];
    __shared__ float red_s[4][2];
    __shared__ float red_d[4][2];
    int tid = threadIdx.x; // 256
    for (int i = tid; i < IN * 64; i += 256) Ws[i] = W[i];
    int node0 = blockIdx.x * 4;
    for (int i = tid; i < 4 * IN; i += 256) {
        int g = i / IN, k = i % IN;
        int n = node0 + g;
        const float* src = FIRST ? xin : g_x;
        xs[g][k] = (n < NN) ? src[(size_t)n * IN + k] : 0.0f;
    }
    __syncthreads();
    int c = tid & 63;
    int g = tid >> 6;
    int n = node0 + g;
    float v = 0.0f;
#pragma unroll
    for (int k = 0; k < IN; k++) v = fmaf(xs[g][k], Ws[k * 64 + c], v);
    float ps = v * att_s[c];
    float pd = v * att_d[c];
#pragma unroll
    for (int o = 16; o; o >>= 1) {
        ps += __shfl_down_sync(0xFFFFFFFFu, ps, o);
        pd += __shfl_down_sync(0xFFFFFFFFu, pd, o);
    }
    if ((tid & 31) == 0) { red_s[g][c >> 5] = ps; red_d[g][c >> 5] = pd; }
    if (n < NN) g_h[(size_t)n * 64 + c] = v;
    __syncthreads();
    if (n < NN && c == 0) {
        g_as[n] = red_s[g][0] + red_s[g][1];
        g_ad[n] = red_d[g][0] + red_d[g][1];
    }
}

// Fused: alpha -> leaky_relu -> exp (no max shift; cancels exactly) -> denom
__global__ void edge_attn(const int* __restrict__ gsrc, const int* __restrict__ gdst) {
    int i = blockIdx.x * blockDim.x + threadIdx.x;
    if (i >= EG) return;
    float a = g_as[gsrc[i]] + g_ad[gdst[i]];
    a = (a >= 0.0f) ? a : 0.2f * a;
    float e = __expf(fminf(a, 80.0f));  // clamp never engages at these magnitudes
    g_alpha[i] = e;
    atomicAdd(&g_denom[gdst[i]], e);
}

// 16 threads per edge; v4 reduction per float4 channel-group
__global__ void edge_scatter(const int* __restrict__ gsrc, const int* __restrict__ gdst) {
    long long idx = (long long)blockIdx.x * blockDim.x + threadIdx.x;
    int e = (int)(idx >> 4);
    if (e >= EG) return;
    int l = (int)(idx & 15);
    int s = gsrc[e], d = gdst[e];
    float w = g_alpha[e] / (g_denom[d] + 1e-16f);
    float4 h = ((const float4*)(g_h + (size_t)s * 64))[l];
    float* od = g_out + (size_t)d * 64 + 4 * l;
    asm volatile("red.global.add.v4.f32 [%0], {%1,%2,%3,%4};"
                 :: "l"(od), "f"(h.x * w), "f"(h.y * w), "f"(h.z * w), "f"(h.w * w) : "memory");
}

__global__ void finalize_node(const float* __restrict__ bias) {
    int i = blockIdx.x * blockDim.x + threadIdx.x;
    if (i >= NN * 64) return;
    g_x[i] = fast_elu(g_out[i] + bias[i & 63]);
}

// ---------------- tf32 tensor-core GEMM: Y[N,1040] = x[N,64] @ B[64,1040] -------
// B[k][n<520]=Wm1[k][n]; B[k][n>=520]=Wm1[64+k][n-520]. Output stored fp16.

__device__ __forceinline__ unsigned f2tf32(float f) {
    unsigned r; asm("cvt.rna.tf32.f32 %0, %1;" : "=r"(r) : "f"(f)); return r;
}

__device__ __forceinline__ void mma_tf32(float c[4],
                                         unsigned a0, unsigned a1, unsigned a2, unsigned a3,
                                         unsigned b0, unsigned b1) {
    asm volatile("mma.sync.aligned.m16n8k8.row.col.f32.tf32.tf32.f32 "
                 "{%0,%1,%2,%3}, {%4,%5,%6,%7}, {%8,%9}, {%0,%1,%2,%3};"
                 : "+f"(c[0]), "+f"(c[1]), "+f"(c[2]), "+f"(c[3])
                 : "r"(a0), "r"(a1), "r"(a2), "r"(a3), "r"(b0), "r"(b1));
}

#define GST 68  // smem row stride (conflict-free: bank = g*4+t, all distinct)

__global__ void gemm_y_tc(const float* __restrict__ Wm1) {
    __shared__ unsigned As[64 * GST];  // 64 rows (M) x 64 cols (K), tf32 bits
    __shared__ unsigned Bs[64 * GST];  // 64 rows (K) x 64 cols (N), tf32 bits
    int bm = blockIdx.y, bn = blockIdx.x;
    int tid = threadIdx.x; // 256
    int m0 = bm * 64, n0 = bn * 64;

    // load A tile (x rows), float4 then cvt
    for (int i = tid; i < 64 * 16; i += 256) {
        int r = i >> 4, v = i & 15;
        int m = m0 + r;
        float4 x = (m < NN) ? ((const float4*)g_x)[(size_t)m * 16 + v]
                            : make_float4(0.f, 0.f, 0.f, 0.f);
        unsigned* dst = &As[r * GST + v * 4];
        dst[0] = f2tf32(x.x); dst[1] = f2tf32(x.y); dst[2] = f2tf32(x.z); dst[3] = f2tf32(x.w);
    }
    // load B tile with column remap
    for (int i = tid; i < 64 * 64; i += 256) {
        int k = i >> 6, nl = i & 63;
        int n = n0 + nl;
        float b = 0.0f;
        if (n < 1040) b = (n < 520) ? Wm1[k * 520 + n] : Wm1[(64 + k) * 520 + (n - 520)];
        Bs[k * GST + nl] = f2tf32(b);
    }
    __syncthreads();

    int warp = tid >> 5, lane = tid & 31;
    int wm = (warp >> 1) * 16;   // 0..48 : warp M-offset (16 rows)
    int wn = (warp & 1) * 32;    // 0,32  : warp N-offset (32 cols = 4 n-frags)
    int g = lane >> 2, t = lane & 3;

    float c[4][4];
#pragma unroll
    for (int ni = 0; ni < 4; ni++)
#pragma unroll
        for (int j = 0; j < 4; j++) c[ni][j] = 0.0f;

#pragma unroll
    for (int k8 = 0; k8 < 8; k8++) {
        int kb = k8 * 8;
        unsigned a0 = As[(wm + g) * GST + kb + t];
        unsigned a1 = As[(wm + g + 8) * GST + kb + t];
        unsigned a2 = As[(wm + g) * GST + kb + t + 4];
        unsigned a3 = As[(wm + g + 8) * GST + kb + t + 4];
#pragma unroll
        for (int ni = 0; ni < 4; ni++) {
            int nb = wn + ni * 8;
            unsigned b0 = Bs[(kb + t) * GST + nb + g];
            unsigned b1 = Bs[(kb + t + 4) * GST + nb + g];
            mma_tf32(c[ni], a0, a1, a2, a3, b0, b1);
        }
    }

    // store fp16 (half2 packed: c0|c1 at (row, col), c2|c3 at (row+8, col))
#pragma unroll
    for (int ni = 0; ni < 4; ni++) {
        int col = n0 + wn + ni * 8 + t * 2;
        if (col >= 1040) continue;
        int r0 = m0 + wm + g;
        int r1 = r0 + 8;
        if (r0 < NN)
            *(__half2*)(g_Yh + (size_t)r0 * 1040 + col) = __floats2half2_rn(c[ni][0], c[ni][1]);
        if (r1 < NN)
            *(__half2*)(g_Yh + (size_t)r1 * 1040 + col) = __floats2half2_rn(c[ni][2], c[ni][3]);
    }
}

// warp per prediction edge; Y is fp16, 8 halfs per uint4 load
__global__ void edge_mlp(const int* __restrict__ esrc, const int* __restrict__ edst,
                         const float* __restrict__ ea,
                         const float* __restrict__ Wm1, const float* __restrict__ bm1,
                         const float* __restrict__ Wm2, const float* __restrict__ bm2,
                         float* __restrict__ out) {
    __shared__ float sB[520], sW2[520], sC0[520], sC1[520];
    int tid = threadIdx.x; // 256
    for (int i = tid; i < 520; i += 256) {
        sB[i]  = bm1[i];
        sW2[i] = Wm2[i];
        sC0[i] = Wm1[128 * 520 + i];
        sC1[i] = Wm1[129 * 520 + i];
    }
    __syncthreads();
    int e = (blockIdx.x * 256 + tid) >> 5;
    if (e >= EE) return;
    int lane = tid & 31;
    int s = esrc[e], d = edst[e];
    float a0 = ea[2 * e], a1 = ea[2 * e + 1];
    const uint4* ys = (const uint4*)(g_Yh + (size_t)s * 1040);        // 2080B row, 16B aligned
    const uint4* yd = (const uint4*)(g_Yh + (size_t)d * 1040 + 520);  // +1040B, 16B aligned
    float acc = 0.0f;
    for (int k = lane; k < 65; k += 32) {   // 65 uint4 = 520 halfs
        uint4 va = ys[k];
        uint4 vb = yd[k];
        const __half2* ha = (const __half2*)&va;
        const __half2* hb = (const __half2*)&vb;
        int ch = k * 8;
#pragma unroll
        for (int j = 0; j < 4; j++) {
            float2 fa = __half22float2(ha[j]);
            float2 fb = __half22float2(hb[j]);
            int c0i = ch + j * 2;
            float v0 = fmaf(a1, sC1[c0i],     fmaf(a0, sC0[c0i],     fa.x + fb.x + sB[c0i]));
            float v1 = fmaf(a1, sC1[c0i + 1], fmaf(a0, sC0[c0i + 1], fa.y + fb.y + sB[c0i + 1]));
            acc = fmaf(fast_elu(v0), sW2[c0i], acc);
            acc = fmaf(fast_elu(v1), sW2[c0i + 1], acc);
        }
    }
#pragma unroll
    for (int o = 16; o; o >>= 1) acc += __shfl_down_sync(0xFFFFFFFFu, acc, o);
    if (lane == 0) out[e] = acc + bm2[0];
}

static void run_gat_layer(const float* xin, bool first,
                          const float* W, const float* as, const float* ad, const float* b,
                          const int* gsrc, const int* gdst) {
    zero_scratch<<<(NN * 64 + 255) / 256, 256>>>();
    if (first) node_transform<true><<<(NN + 3) / 4, 256>>>(xin, W, as, ad);
    else       node_transform<false><<<(NN + 3) / 4, 256>>>(xin, W, as, ad);
    edge_attn<<<(EG + 255) / 256, 256>>>(gsrc, gdst);
    edge_scatter<<<((long long)EG * 16 + 255) / 256, 256>>>(gsrc, gdst);
    finalize_node<<<(NN * 64 + 255) / 256, 256>>>(b);
}

extern "C" void kernel_launch(void* const* d_in, const int* in_sizes, int n_in,
                              void* d_out, int out_size) {
    const float* pos   = (const float*)d_in[0];
    const int*   eidx  = (const int*)d_in[1];
    const int*   geidx = (const int*)d_in[2];
    const float* eattr = (const float*)d_in[3];
    const float* W0    = (const float*)d_in[4];
    const float* as0   = (const float*)d_in[5];
    const float* ad0   = (const float*)d_in[6];
    const float* b0    = (const float*)d_in[7];
    const float* W1    = (const float*)d_in[8];
    const float* as1   = (const float*)d_in[9];
    const float* ad1   = (const float*)d_in[10];
    const float* b1    = (const float*)d_in[11];
    const float* Wm1   = (const float*)d_in[12];
    const float* bm1   = (const float*)d_in[13];
    const float* Wm2   = (const float*)d_in[14];
    const float* bm2   = (const float*)d_in[15];
    float* out = (float*)d_out;

    const int* gsrc = geidx;
    const int* gdst = geidx + EG;
    const int* esrc = eidx;
    const int* edst = eidx + EE;

    run_gat_layer(pos, true,  W0, as0, ad0, b0, gsrc, gdst);
    run_gat_layer(nullptr, false, W1, as1, ad1, b1, gsrc, gdst);

    dim3 ggrid(17, (NN + 63) / 64);   // N tiles x M tiles
    gemm_y_tc<<<ggrid, 256>>>(Wm1);

    edge_mlp<<<((long long)EE * 32 + 255) / 256, 256>>>(esrc, edst, eattr, Wm1, bm1, Wm2, bm2, out);
}